// round 7
// baseline (speedup 1.0000x reference)
#include <cuda_runtime.h>
#include <cuda_bf16.h>
#include <stdint.h>

// Problem constants
#define NB      32
#define NN      64
#define MV      2080          // NN*(NN+1)/2
#define MAIN    2048
#define NEXTRA  32
#define TOPK    5
#define NEIGHBOR 16
#define NEGATIVE 16
#define TOTAL   85            // TOPK*(NEIGHBOR+1)
#define KOUT    101           // NEGATIVE + TOTAL
#define DFEAT   512
#define NT      512           // block size

// dynamic smem layout (byte offsets)
#define OFF_FKEY    0          // u64[2080]  16640
#define OFF_MKEY    16640      // u64[2048]  16384
#define OFF_EXTRA   33024      // u64[32]      256
#define OFF_MOM     33280      // u32[2080]   8320
#define OFF_RR      41600      // u8[2080]
#define OFF_CC      43680      // u8[2080]
#define OFF_SUP     45760      // u8[2080]
#define OFF_SEL     47840      // u8[2080]
#define OFF_UNSUP   49920      // u16[2080]   4160
#define OFF_SELIDX  54080      // u16[96]
#define OFF_WSUM    54272      // int[17] pad 136
#define OFF_FR      54408      // int[101]
#define OFF_FC      54812      // int[101]
#define SMEM_BYTES  55296

#define BAR128() asm volatile("bar.sync 1, 128;" ::: "memory")
#define BAR160() asm volatile("bar.sync 2, 160;" ::: "memory")

typedef unsigned long long u64;

__device__ __forceinline__ unsigned sw16(unsigned i) { return i ^ ((i >> 4) & 15u); }

__device__ __forceinline__ void casv(u64& a, u64& b, bool dir) {
    // dir true -> descending (a >= b)
    u64 x = a, y = b;
    bool sw = dir ? (x < y) : (x > y);
    a = sw ? y : x;
    b = sw ? x : y;
}

// intra-thread levels j = 8,4,2,1 with uniform direction
__device__ __forceinline__ void intra4(u64 e[16], bool dir) {
#pragma unroll
    for (int j = 8; j >= 1; j >>= 1)
#pragma unroll
        for (int v = 0; v < 16; v++)
            if (!(v & j)) casv(e[v], e[v | j], dir);
}

// one shuffle level: partner lane = lane ^ lm  (element j = lm*16)
__device__ __forceinline__ void shfl_lv(u64 e[16], int lane, int lm, bool dirU) {
    bool keepMax = ((lane & lm) == 0) == dirU;
#pragma unroll
    for (int v = 0; v < 16; v++) {
        u64 p = __shfl_xor_sync(0xffffffffu, e[v], lm);
        u64 mx = e[v] > p ? e[v] : p;
        u64 mn = e[v] > p ? p : e[v];
        e[v] = keepMax ? mx : mn;
    }
}

// cross-warp smem level j (512 or 1024) of merge k over 2048 elems; 128 threads
__device__ __forceinline__ void cross_pass(u64* mk, int k, int j, int lgj, int tid) {
#pragma unroll
    for (int u = 0; u < 8; u++) {
        int q = tid * 8 + u;                          // 1024 pairs
        int i = ((q >> lgj) << (lgj + 1)) | (q & (j - 1));
        unsigned a0 = sw16((unsigned)i);
        unsigned a1 = a0 ^ (unsigned)j;               // sw commutes for j>=512
        u64 x = mk[a0], y = mk[a1];
        bool dir = ((i & k) == 0);
        bool swp = dir ? (x < y) : (x > y);
        if (swp) { mk[a0] = y; mk[a1] = x; }
    }
}

template<bool WANT_TRUE>
__device__ __forceinline__ int compact512(const unsigned char* flags,
                                          unsigned short* out, int* wsum) {
    int tid = threadIdx.x, lane = tid & 31, wid = tid >> 5;   // 16 warps
    bool pr[5]; int local = 0;
#pragma unroll
    for (int u = 0; u < 5; u++) {
        int j = 5 * tid + u;
        bool f = (j < MV) && ((flags[j] != 0) == WANT_TRUE);
        pr[u] = f; local += (int)f;
    }
    int x = local;
#pragma unroll
    for (int d = 1; d < 32; d <<= 1) {
        int y = __shfl_up_sync(0xffffffffu, x, d);
        if (lane >= d) x += y;
    }
    if (lane == 31) wsum[wid] = x;    // inclusive warp totals
    __syncthreads();
    if (wid == 0) {
        int v = (lane < 16) ? wsum[lane] : 0;
        int xx = v;
#pragma unroll
        for (int d = 1; d < 32; d <<= 1) {
            int y = __shfl_up_sync(0xffffffffu, xx, d);
            if (lane >= d) xx += y;
        }
        if (lane < 16) wsum[lane] = xx - v;    // exclusive
        if (lane == 15) wsum[16] = xx;         // grand total
    }
    __syncthreads();
    int base = wsum[wid] + x - local;
#pragma unroll
    for (int u = 0; u < 5; u++) {
        if (pr[u]) out[base++] = (unsigned short)(5 * tid + u);
    }
    int total = wsum[16];
    __syncthreads();   // protect wsum for reuse
    return total;
}

__global__ __launch_bounds__(NT, 1)
void aps_kernel(const float* __restrict__ score_pred,
                const float* __restrict__ map2d,
                const float* __restrict__ offset_gt,
                const float* __restrict__ tmap,
                float* __restrict__ out) {
    extern __shared__ char smem[];
    u64*  fkey  = (u64*)(smem + OFF_FKEY);
    u64*  mkey  = (u64*)(smem + OFF_MKEY);
    u64*  extra = (u64*)(smem + OFF_EXTRA);
    unsigned*       mom  = (unsigned*)      (smem + OFF_MOM);
    unsigned char*  rr   = (unsigned char*) (smem + OFF_RR);
    unsigned char*  cc   = (unsigned char*) (smem + OFF_CC);
    unsigned char*  sup  = (unsigned char*) (smem + OFF_SUP);
    unsigned char*  sel  = (unsigned char*) (smem + OFF_SEL);
    unsigned short* unsupIdx = (unsigned short*)(smem + OFF_UNSUP);
    unsigned short* selIdx   = (unsigned short*)(smem + OFF_SELIDX);
    int* wsum = (int*)(smem + OFF_WSUM);
    int* fr   = (int*)(smem + OFF_FR);
    int* fc   = (int*)(smem + OFF_FC);

    const int b    = blockIdx.x;
    const int tid  = threadIdx.x;
    const int lane = tid & 31, wid = tid >> 5;

    // --- 1. (r,c) tables for triu mask in row-major nonzero order ---
    if (tid < NN) {
        int r = tid;
        int base = r * NN - (r * (r - 1)) / 2;
        for (int c = r; c < NN; c++) {
            int p = base + (c - r);
            rr[p] = (unsigned char)r;
            cc[p] = (unsigned char)c;
        }
    }
    __syncthreads();

    // --- 2. build keys (all 512 threads, coalesced). key=(ord_f32<<32)|(2079-p) ---
    for (int p = tid; p < MAIN; p += NT) {
        int r = rr[p], c = cc[p];
        float s = score_pred[((size_t)b * NN + r) * NN + c];
        unsigned ub = __float_as_uint(s);
        ub = (ub & 0x80000000u) ? ~ub : (ub | 0x80000000u);
        mkey[sw16((unsigned)p)] = ((u64)ub << 32) | (unsigned)(2079 - p);
    }
    if (tid < NEXTRA) {
        int p = MAIN + tid;
        int r = rr[p], c = cc[p];
        float s = score_pred[((size_t)b * NN + r) * NN + c];
        unsigned ub = __float_as_uint(s);
        ub = (ub & 0x80000000u) ? ~ub : (ub | 0x80000000u);
        extra[tid] = ((u64)ub << 32) | (unsigned)(2079 - p);
    }
    __syncthreads();

    // --- 3. sort: warps 0-3 (V=16) + warp 4 (extras) ---
    if (wid < 4) {
        u64 e[16];
#pragma unroll
        for (int v = 0; v < 16; v++) e[v] = mkey[sw16((unsigned)(tid * 16 + v))];

        // k = 2..8 : direction varies with v
#pragma unroll
        for (int k = 2; k <= 8; k <<= 1)
#pragma unroll
            for (int j = k >> 1; j >= 1; j >>= 1)
#pragma unroll
                for (int v = 0; v < 16; v++)
                    if (!(v & j)) casv(e[v], e[v | j], ((v & k) == 0));
        // k = 16
        intra4(e, (lane & 1) == 0);
        // k = 32..256 : shuffles + intra
#pragma unroll
        for (int k = 32; k <= 256; k <<= 1) {
            bool dir = ((lane & (k >> 4)) == 0);
#pragma unroll
            for (int lm = (k >> 5); lm >= 1; lm >>= 1) shfl_lv(e, lane, lm, dir);
            intra4(e, dir);
        }
        // k = 512 : still fully in-warp (j<=256)
        {
            bool dir = ((tid & 32) == 0);
#pragma unroll
            for (int lm = 16; lm >= 1; lm >>= 1) shfl_lv(e, lane, lm, dir);
            intra4(e, dir);
        }
        // k = 1024 : j=512 via smem, rest in registers
#pragma unroll
        for (int v = 0; v < 16; v++) mkey[sw16((unsigned)(tid * 16 + v))] = e[v];
        BAR128();
        cross_pass(mkey, 1024, 512, 9, tid);
        BAR128();
#pragma unroll
        for (int v = 0; v < 16; v++) e[v] = mkey[sw16((unsigned)(tid * 16 + v))];
        {
            bool dir = ((tid & 64) == 0);
#pragma unroll
            for (int lm = 16; lm >= 1; lm >>= 1) shfl_lv(e, lane, lm, dir);
            intra4(e, dir);
        }
        // k = 2048 : j=1024,512 via smem, rest in registers
#pragma unroll
        for (int v = 0; v < 16; v++) mkey[sw16((unsigned)(tid * 16 + v))] = e[v];
        BAR128();
        cross_pass(mkey, 2048, 1024, 10, tid);
        BAR128();
        cross_pass(mkey, 2048, 512, 9, tid);
        BAR128();
#pragma unroll
        for (int v = 0; v < 16; v++) e[v] = mkey[sw16((unsigned)(tid * 16 + v))];
        {
            bool dir = true;
#pragma unroll
            for (int lm = 16; lm >= 1; lm >>= 1) shfl_lv(e, lane, lm, dir);
            intra4(e, dir);
        }
        // publish sorted main run
#pragma unroll
        for (int v = 0; v < 16; v++) mkey[sw16((unsigned)(tid * 16 + v))] = e[v];
        BAR160();
        // rank-merge: scatter mains into fkey
#pragma unroll
        for (int v = 0; v < 16; v++) {
            u64 x = e[v];
            int lo = 0, hiS = NEXTRA;            // count extras > x (desc)
            while (lo < hiS) {
                int mid = (lo + hiS) >> 1;
                if (extra[mid] > x) lo = mid + 1; else hiS = mid;
            }
            fkey[tid * 16 + v + lo] = x;
        }
    } else if (wid == 4) {
        // warp 4: 32-element shuffle bitonic sort (descending)
        u64 x = extra[lane];
#pragma unroll
        for (int k2 = 2; k2 <= 32; k2 <<= 1) {
            bool dirk = ((lane & k2) == 0);
#pragma unroll
            for (int j2 = 16; j2 >= 1; j2 >>= 1) {
                if (j2 < k2) {
                    u64 pr = __shfl_xor_sync(0xffffffffu, x, j2);
                    bool keepMax = (((lane & j2) == 0) == dirk);
                    u64 mx = x > pr ? x : pr;
                    u64 mn = x > pr ? pr : x;
                    x = keepMax ? mx : mn;
                }
            }
        }
        extra[lane] = x;
        BAR160();
        // rank-merge: scatter extras into fkey (binary search over logical mkey)
        int lo = 0, hiS = MAIN;
        while (lo < hiS) {
            int mid = (lo + hiS) >> 1;
            if (mkey[sw16((unsigned)mid)] > x) lo = mid + 1; else hiS = mid;
        }
        fkey[lo + lane] = x;
    }
    __syncthreads();

    // --- 4. sorted packed moments + clear bitmaps ---
    for (int i = tid; i < MV; i += NT) {
        int orig = 2079 - (int)(unsigned)(fkey[i] & 0xFFFFFFFFull);
        unsigned s = rr[orig];
        unsigned en = (unsigned)cc[orig] + 1u;
        mom[i] = s | (en << 16);
        sup[i] = 0; sel[i] = 0;
    }
    __syncthreads();

    // --- 5. NMS selection loop (warp 0 only) ---
    if (wid == 0) {
        int i = 0, cnt = 0;
        while (cnt < TOPK) {
            int piv = -1;
            for (int base = i; base < MV - 1; base += 32) {
                int j = base + lane;
                bool ok = (j < MV - 1) && (sup[j] == 0);
                unsigned bl = __ballot_sync(0xffffffffu, ok);
                if (bl) { piv = base + __ffs(bl) - 1; break; }
            }
            if (piv < 0) break;
            unsigned mp = mom[piv];
            int s_i = (int)(mp & 0xffffu), e_i = (int)(mp >> 16);

            u64 mlo = 0ull; unsigned mhi = 0u;
            int localCount = 0;
#pragma unroll 13
            for (int u = 0; u < 65; u++) {
                int j = lane * 65 + u;
                bool match = false;
                if (j < MV && j > piv) {
                    unsigned m = mom[j];
                    int sj = (int)(m & 0xffffu), ej = (int)(m >> 16);
                    int inter = min(ej, e_i) - max(sj, s_i);
                    int uni   = max(ej, e_i) - min(sj, s_i);
                    match = (2 * inter > uni);
                }
                if (match) {
                    localCount++;
                    if (u < 64) mlo |= (1ull << u); else mhi |= 1u;
                }
            }
            int x = localCount;
#pragma unroll
            for (int d = 1; d < 32; d <<= 1) {
                int y = __shfl_up_sync(0xffffffffu, x, d);
                if (lane >= d) x += y;
            }
            int run = x - localCount;
#pragma unroll 13
            for (int u = 0; u < 65; u++) {
                bool match = (u < 64) ? (((mlo >> u) & 1ull) != 0ull) : (mhi != 0u);
                if (match) {
                    int j = lane * 65 + u;
                    sup[j] = 1;
                    run++;
                    if (run <= NEIGHBOR) sel[j] = 1;
                }
            }
            if (lane == 0) { sup[piv] = 1; sel[piv] = 1; }
            __syncwarp();
            cnt++;
            i = piv + 1;
        }
    }
    __syncthreads();

    // --- 6. stable compactions ---
    int nUnsup = compact512<false>(sup, unsupIdx, wsum);
    int nSel   = compact512<true >(sel, selIdx,   wsum);

    // --- 7. final index assembly + small outputs ---
    float* feat = out;
    float* se   = out + (size_t)NB * KOUT * DFEAT;
    float* off  = se  + (size_t)NB * KOUT * 2;
    float* sc   = off + (size_t)NB * KOUT * 2;

    if (tid < KOUT) {
        int k = tid;
        int val;
        if (k < NEGATIVE) {
            int pos = nUnsup - 1 - k;
            if (pos < 0) pos = 0;
            val = (pos < nUnsup) ? (int)unsupIdx[pos] : (MV - 1);
        } else {
            int p = k - NEGATIVE;
            int pad = TOTAL - nSel;
            if (p < pad) {
                val = (p < nUnsup) ? (int)unsupIdx[p] : (MV - 1);
            } else {
                val = (int)selIdx[p - pad];
            }
        }
        int orig = 2079 - (int)(unsigned)(fkey[val] & 0xFFFFFFFFull);
        int r = rr[orig], c = cc[orig];
        fr[k] = r; fc[k] = c;

        size_t o = (size_t)b * KOUT + k;
        se[o * 2 + 0] = (float)r;
        se[o * 2 + 1] = (float)(c + 1);
        size_t cell = ((size_t)b * NN + r) * NN + c;
        off[o * 2 + 0] = offset_gt[cell * 2 + 0];
        off[o * 2 + 1] = offset_gt[cell * 2 + 1];
        sc[o] = tmap[cell];
    }
    __syncthreads();

    // --- 8. feature gather (float4, coalesced 2KB rows) ---
    const float4* src = (const float4*)map2d;
    float4* dst = (float4*)feat;
    const int VEC = DFEAT / 4;   // 128
    for (int t = tid; t < KOUT * VEC; t += NT) {
        int k = t >> 7;
        int d = t & (VEC - 1);
        int r = fr[k], c = fc[k];
        dst[((size_t)b * KOUT + k) * VEC + d] =
            src[(((size_t)b * NN + r) * NN + c) * VEC + d];
    }
}

extern "C" void kernel_launch(void* const* d_in, const int* in_sizes, int n_in,
                              void* d_out, int out_size) {
    const float* score_pred = (const float*)d_in[0];
    // d_in[1] = map2d_mask (deterministic triu(ones)) — computed analytically
    const float* map2d      = (const float*)d_in[2];
    const float* offset_gt  = (const float*)d_in[3];
    const float* tmap       = (const float*)d_in[4];
    float* out = (float*)d_out;

    cudaFuncSetAttribute(aps_kernel, cudaFuncAttributeMaxDynamicSharedMemorySize,
                         SMEM_BYTES);
    aps_kernel<<<NB, NT, SMEM_BYTES>>>(score_pred, map2d, offset_gt, tmap, out);
}

// round 9
// speedup vs baseline: 2.2241x; 2.2241x over previous
#include <cuda_runtime.h>
#include <cuda_bf16.h>
#include <stdint.h>

// Problem constants
#define NB      32
#define NN      64
#define MV      2080          // NN*(NN+1)/2
#define MAIN    2048
#define NEXTRA  32
#define TOPK    5
#define NEIGHBOR 16
#define NEGATIVE 16
#define TOTAL   85            // TOPK*(NEIGHBOR+1)
#define KOUT    101           // NEGATIVE + TOTAL
#define DFEAT   512
#define NT      1024

// dynamic smem layout (byte offsets)
#define OFF_FKEY    0          // u64[2080]  16640
#define OFF_MKEY    16640      // u64[2048]  16384
#define OFF_EXTRA   33024      // u64[32]      256
#define OFF_MOM     33280      // u32[2080]   8320
#define OFF_RR      41600      // u8[2080]
#define OFF_CC      43680      // u8[2080]
#define OFF_SUP     45760      // u8[2080]
#define OFF_SEL     47840      // u8[2080]
#define OFF_UNSUP   49920      // u16[2080]   4160
#define OFF_SELIDX  54080      // u16[96]
#define OFF_WSUM    54272      // int[34]     136
#define OFF_FR      54408      // int[101]    404
#define OFF_FC      54812      // int[101]    404  -> 55216
#define OFF_WORDS   55216      // u32[65]     260
#define OFF_PFX     55480      // int[66]     264
#define OFF_PIV     55744      // int[4]       16
#define SMEM_BYTES  55808

typedef unsigned long long u64;

__device__ __forceinline__ void cas64(u64& a, u64& b, bool dir) {
    u64 x = a, y = b;
    bool sw = dir ? (x < y) : (x > y);
    a = sw ? y : x;
    b = sw ? x : y;
}

template<int J0>
__device__ __forceinline__ void reg_stages(u64 e[4], int tid, int lane, int k) {
    const int base = tid * 4;
    const bool dirU = ((base & k) == 0);
#pragma unroll
    for (int j = J0; j >= 4; j >>= 1) {
        int lm = j >> 2;
        bool lower = ((lane & lm) == 0);
        bool keepMax = (lower == dirU);
#pragma unroll
        for (int v = 0; v < 4; v++) {
            u64 p = __shfl_xor_sync(0xffffffffu, e[v], lm);
            u64 mx = e[v] > p ? e[v] : p;
            u64 mn = e[v] > p ? p : e[v];
            e[v] = keepMax ? mx : mn;
        }
    }
    if (J0 >= 2) {
        cas64(e[0], e[2], dirU);
        cas64(e[1], e[3], dirU);
    }
    if (k == 2) {
        cas64(e[0], e[1], true);
        cas64(e[2], e[3], false);
    } else {
        cas64(e[0], e[1], dirU);
        cas64(e[2], e[3], dirU);
    }
}

// Two levels (2j, j) of merge k over 2048 elems; 512 sorter threads.
__device__ __forceinline__ void pass2(u64* a, int k, int j, int lg, int tid) {
    int low  = tid & (j - 1);
    int hi   = tid >> lg;
    int base = (hi << (lg + 2)) | low;
    u64 e0 = a[base], e1 = a[base + j], e2 = a[base + 2 * j], e3 = a[base + 3 * j];
    bool dir = ((base & k) == 0);
    cas64(e0, e2, dir); cas64(e1, e3, dir);
    cas64(e0, e1, dir); cas64(e2, e3, dir);
    a[base] = e0; a[base + j] = e1; a[base + 2 * j] = e2; a[base + 3 * j] = e3;
}

__device__ __forceinline__ void single128(u64* a, int k, int tid) {
#pragma unroll
    for (int rep = 0; rep < 2; rep++) {
        int p = tid + rep * 512;
        int i = ((p >> 7) << 8) | (p & 127);
        u64 x = a[i], y = a[i + 128];
        bool dir = ((i & k) == 0);
        bool sw = dir ? (x < y) : (x > y);
        if (sw) { a[i] = y; a[i + 128] = x; }
    }
}

template<bool WANT_TRUE>
__device__ __forceinline__ int compact2080(const unsigned char* flags,
                                           unsigned short* out, int* wsum) {
    int tid = threadIdx.x, lane = tid & 31, wid = tid >> 5;
    bool pr[3]; int local = 0;
#pragma unroll
    for (int u = 0; u < 3; u++) {
        int j = 3 * tid + u;
        bool f = (j < MV) && ((flags[j] != 0) == WANT_TRUE);
        pr[u] = f; local += (int)f;
    }
    int x = local;
#pragma unroll
    for (int d = 1; d < 32; d <<= 1) {
        int y = __shfl_up_sync(0xffffffffu, x, d);
        if (lane >= d) x += y;
    }
    if (lane == 31) wsum[wid] = x;
    __syncthreads();
    if (wid == 0) {
        int v = wsum[lane];
        int xx = v;
#pragma unroll
        for (int d = 1; d < 32; d <<= 1) {
            int y = __shfl_up_sync(0xffffffffu, xx, d);
            if (lane >= d) xx += y;
        }
        wsum[lane] = xx - v;
        if (lane == 31) wsum[32] = xx;
    }
    __syncthreads();
    int base = wsum[wid] + x - local;
#pragma unroll
    for (int u = 0; u < 3; u++) {
        if (pr[u]) out[base++] = (unsigned short)(3 * tid + u);
    }
    int total = wsum[32];
    __syncthreads();
    return total;
}

__global__ __launch_bounds__(NT, 1)
void aps_kernel(const float* __restrict__ score_pred,
                const float* __restrict__ map2d,
                const float* __restrict__ offset_gt,
                const float* __restrict__ tmap,
                float* __restrict__ out) {
    extern __shared__ char smem[];
    u64*  fkey  = (u64*)(smem + OFF_FKEY);
    u64*  mkey  = (u64*)(smem + OFF_MKEY);
    u64*  extra = (u64*)(smem + OFF_EXTRA);
    unsigned*       mom  = (unsigned*)      (smem + OFF_MOM);
    unsigned char*  rr   = (unsigned char*) (smem + OFF_RR);
    unsigned char*  cc   = (unsigned char*) (smem + OFF_CC);
    unsigned char*  sup  = (unsigned char*) (smem + OFF_SUP);
    unsigned char*  sel  = (unsigned char*) (smem + OFF_SEL);
    unsigned short* unsupIdx = (unsigned short*)(smem + OFF_UNSUP);
    unsigned short* selIdx   = (unsigned short*)(smem + OFF_SELIDX);
    int* wsum = (int*)(smem + OFF_WSUM);
    int* fr   = (int*)(smem + OFF_FR);
    int* fc   = (int*)(smem + OFF_FC);
    unsigned* words = (unsigned*)(smem + OFF_WORDS);
    int* pfx  = (int*)(smem + OFF_PFX);
    int* pivinfo = (int*)(smem + OFF_PIV);

    const int b    = blockIdx.x;
    const int tid  = threadIdx.x;
    const int lane = tid & 31, wid = tid >> 5;
    const bool sorter = (wid < 16);

    // --- 1. (r,c) tables ---
    if (tid < NN) {
        int r = tid;
        int base = r * NN - (r * (r - 1)) / 2;
        for (int c = r; c < NN; c++) {
            int p = base + (c - r);
            rr[p] = (unsigned char)r;
            cc[p] = (unsigned char)c;
        }
    }
    __syncthreads();

    // --- 2. build keys in registers: (orderable_f32 << 32) | (2079 - p) ---
    u64 e[4];
    if (sorter) {
#pragma unroll
        for (int v = 0; v < 4; v++) {
            int p = tid * 4 + v;
            int r = rr[p], c = cc[p];
            float s = score_pred[((size_t)b * NN + r) * NN + c];
            unsigned ub = __float_as_uint(s);
            ub = (ub & 0x80000000u) ? ~ub : (ub | 0x80000000u);
            e[v] = ((u64)ub << 32) | (unsigned)(2079 - p);
        }
        reg_stages<1 >(e, tid, lane, 2);
        reg_stages<2 >(e, tid, lane, 4);
        reg_stages<4 >(e, tid, lane, 8);
        reg_stages<8 >(e, tid, lane, 16);
        reg_stages<16>(e, tid, lane, 32);
        reg_stages<32>(e, tid, lane, 64);
        reg_stages<64>(e, tid, lane, 128);
    } else if (wid == 16) {
        int p = MAIN + lane;
        int r = rr[p], c = cc[p];
        float s = score_pred[((size_t)b * NN + r) * NN + c];
        unsigned ub = __float_as_uint(s);
        ub = (ub & 0x80000000u) ? ~ub : (ub | 0x80000000u);
        u64 x = ((u64)ub << 32) | (unsigned)(2079 - p);
#pragma unroll
        for (int k2 = 2; k2 <= 32; k2 <<= 1) {
            bool dirk = ((lane & k2) == 0);
#pragma unroll
            for (int j2 = 16; j2 >= 1; j2 >>= 1) {
                if (j2 < k2) {
                    u64 pr = __shfl_xor_sync(0xffffffffu, x, j2);
                    bool keepMax = (((lane & j2) == 0) == dirk);
                    u64 mx = x > pr ? x : pr;
                    u64 mn = x > pr ? pr : x;
                    x = keepMax ? mx : mn;
                }
            }
        }
        extra[lane] = x;
    }

    // --- 3. merges k=256..2048 ---
#pragma unroll 1
    for (int k = 256; k <= MAIN; k <<= 1) {
        if (sorter) {
#pragma unroll
            for (int v = 0; v < 4; v++) mkey[tid * 4 + v] = e[v];
        }
        __syncthreads();
        if (k == 256) {
            if (sorter) single128(mkey, k, tid);
        } else if (k == 512) {
            if (sorter) pass2(mkey, k, 128, 7, tid);
        } else if (k == 1024) {
            if (sorter) pass2(mkey, k, 256, 8, tid);
            __syncthreads();
            if (sorter) single128(mkey, k, tid);
        } else {
            if (sorter) pass2(mkey, k, 512, 9, tid);
            __syncthreads();
            if (sorter) pass2(mkey, k, 128, 7, tid);
        }
        __syncthreads();
        if (sorter) {
#pragma unroll
            for (int v = 0; v < 4; v++) e[v] = mkey[tid * 4 + v];
            reg_stages<64>(e, tid, lane, k);
        }
    }

    // --- 3d. publish + rank merge with extras ---
    if (sorter) {
#pragma unroll
        for (int v = 0; v < 4; v++) mkey[tid * 4 + v] = e[v];
    }
    __syncthreads();
    if (sorter) {
#pragma unroll
        for (int v = 0; v < 4; v++) {
            u64 x = e[v];
            int lo = 0, hiS = NEXTRA;
            while (lo < hiS) {
                int mid = (lo + hiS) >> 1;
                if (extra[mid] > x) lo = mid + 1; else hiS = mid;
            }
            fkey[tid * 4 + v + lo] = x;
        }
    } else if (wid == 16) {
        u64 x = extra[lane];
        int lo = 0, hiS = MAIN;
        while (lo < hiS) {
            int mid = (lo + hiS) >> 1;
            if (mkey[mid] > x) lo = mid + 1; else hiS = mid;
        }
        fkey[lo + lane] = x;
    }
    __syncthreads();

    // --- 4. sorted packed moments + clear bitmaps ---
    for (int i = tid; i < MV; i += NT) {
        int orig = 2079 - (int)(unsigned)(fkey[i] & 0xFFFFFFFFull);
        unsigned s = rr[orig];
        unsigned en = (unsigned)cc[orig] + 1u;
        mom[i] = s | (en << 16);
        sup[i] = 0; sel[i] = 0;
    }
    if (tid == 0) pivinfo[1] = 0;   // next pivot search start
    __syncthreads();

    // --- 5. NMS: block-parallel per-pivot ---
    const int j1 = tid;             // < 2048 always valid elem (MV>2048? yes 2080)
    const int j2 = tid + 1024;      // < 2048
    const int j3 = 2048 + tid;      // valid only for tid < 32
#pragma unroll 1
    for (int iter = 0; iter < TOPK; iter++) {
        // pivot scan (warp 0)
        if (wid == 0) {
            int i0 = pivinfo[1];
            int piv = -1;
            for (int base = i0; base < MV - 1; base += 32) {
                int j = base + lane;
                bool ok = (j < MV - 1) && (sup[j] == 0);
                unsigned bl = __ballot_sync(0xffffffffu, ok);
                if (bl) { piv = base + __ffs(bl) - 1; break; }
            }
            if (lane == 0) {
                pivinfo[0] = piv;
                if (piv >= 0) {
                    pivinfo[2] = (int)mom[piv];
                    pivinfo[1] = piv + 1;
                }
            }
        }
        __syncthreads();
        int piv = pivinfo[0];
        if (piv < 0) break;
        unsigned mp = (unsigned)pivinfo[2];
        int s_i = (int)(mp & 0xffffu), e_i = (int)(mp >> 16);

        // match ballots -> 65-word bitmap
        auto matchf = [&](int j) -> bool {
            if (j <= piv || j >= MV) return false;
            unsigned m = mom[j];
            int sj = (int)(m & 0xffffu), ej = (int)(m >> 16);
            int inter = min(ej, e_i) - max(sj, s_i);
            int uni   = max(ej, e_i) - min(sj, s_i);
            return (2 * inter > uni);
        };
        bool m1 = matchf(j1);
        bool m2 = matchf(j2);
        unsigned b1 = __ballot_sync(0xffffffffu, m1);
        unsigned b2 = __ballot_sync(0xffffffffu, m2);
        if (lane == 0) { words[wid] = b1; words[32 + wid] = b2; }
        bool m3 = false;
        if (wid == 0) {
            m3 = matchf(j3);
            unsigned b3 = __ballot_sync(0xffffffffu, m3);
            if (lane == 0) words[64] = b3;
        }
        __syncthreads();
        // prefix over 65 words (warp 0)
        if (wid == 0) {
            int c0 = __popc(words[lane]);
            int x0 = c0;
#pragma unroll
            for (int d = 1; d < 32; d <<= 1) {
                int y = __shfl_up_sync(0xffffffffu, x0, d);
                if (lane >= d) x0 += y;
            }
            pfx[lane] = x0 - c0;
            int tot0 = __shfl_sync(0xffffffffu, x0, 31);
            int c1 = __popc(words[32 + lane]);
            int x1 = c1;
#pragma unroll
            for (int d = 1; d < 32; d <<= 1) {
                int y = __shfl_up_sync(0xffffffffu, x1, d);
                if (lane >= d) x1 += y;
            }
            pfx[32 + lane] = tot0 + x1 - c1;
            if (lane == 31) pfx[64] = tot0 + x1;
        }
        __syncthreads();
        // write sup/sel using global ranks
        auto dowrite = [&](int j, bool m) {
            if (m) {
                int w = j >> 5, bit = j & 31;
                unsigned below = words[w] & (0xffffffffu >> (31 - bit)); // bits 0..bit
                int rank = pfx[w] + __popc(below);   // inclusive rank, 1-based
                sup[j] = 1;
                if (rank <= NEIGHBOR) sel[j] = 1;
            }
        };
        dowrite(j1, m1);
        dowrite(j2, m2);
        if (wid == 0) dowrite(j3, m3);
        if (tid == 0) { sup[piv] = 1; sel[piv] = 1; }
        __syncthreads();
    }
    __syncthreads();

    // --- 6. stable compactions ---
    int nUnsup = compact2080<false>(sup, unsupIdx, wsum);
    int nSel   = compact2080<true >(sel, selIdx,   wsum);

    // --- 7. final index assembly + small outputs ---
    float* feat = out;
    float* se   = out + (size_t)NB * KOUT * DFEAT;
    float* off  = se  + (size_t)NB * KOUT * 2;
    float* sc   = off + (size_t)NB * KOUT * 2;

    if (tid < KOUT) {
        int k = tid;
        int val;
        if (k < NEGATIVE) {
            int pos = nUnsup - 1 - k;
            if (pos < 0) pos = 0;
            val = (pos < nUnsup) ? (int)unsupIdx[pos] : (MV - 1);
        } else {
            int p = k - NEGATIVE;
            int pad = TOTAL - nSel;
            if (p < pad) {
                val = (p < nUnsup) ? (int)unsupIdx[p] : (MV - 1);
            } else {
                val = (int)selIdx[p - pad];
            }
        }
        int orig = 2079 - (int)(unsigned)(fkey[val] & 0xFFFFFFFFull);
        int r = rr[orig], c = cc[orig];
        fr[k] = r; fc[k] = c;

        size_t o = (size_t)b * KOUT + k;
        se[o * 2 + 0] = (float)r;
        se[o * 2 + 1] = (float)(c + 1);
        size_t cell = ((size_t)b * NN + r) * NN + c;
        off[o * 2 + 0] = offset_gt[cell * 2 + 0];
        off[o * 2 + 1] = offset_gt[cell * 2 + 1];
        sc[o] = tmap[cell];
    }
    __syncthreads();

    // --- 8. feature gather (float4) ---
    const float4* src = (const float4*)map2d;
    float4* dst = (float4*)feat;
    const int VEC = DFEAT / 4;   // 128
    for (int t = tid; t < KOUT * VEC; t += NT) {
        int k = t >> 7;
        int d = t & (VEC - 1);
        int r = fr[k], c = fc[k];
        dst[((size_t)b * KOUT + k) * VEC + d] =
            src[(((size_t)b * NN + r) * NN + c) * VEC + d];
    }
}

extern "C" void kernel_launch(void* const* d_in, const int* in_sizes, int n_in,
                              void* d_out, int out_size) {
    const float* score_pred = (const float*)d_in[0];
    // d_in[1] = map2d_mask (deterministic triu(ones)) — computed analytically
    const float* map2d      = (const float*)d_in[2];
    const float* offset_gt  = (const float*)d_in[3];
    const float* tmap       = (const float*)d_in[4];
    float* out = (float*)d_out;

    cudaFuncSetAttribute(aps_kernel, cudaFuncAttributeMaxDynamicSharedMemorySize,
                         SMEM_BYTES);
    aps_kernel<<<NB, NT, SMEM_BYTES>>>(score_pred, map2d, offset_gt, tmap, out);
}

// round 10
// speedup vs baseline: 2.3778x; 1.0691x over previous
#include <cuda_runtime.h>
#include <cuda_bf16.h>
#include <stdint.h>

// Problem constants
#define NB      32
#define NN      64
#define MV      2080          // NN*(NN+1)/2
#define MAIN    2048
#define NEXTRA  32
#define TOPK    5
#define NEIGHBOR 16
#define NEGATIVE 16
#define TOTAL   85            // TOPK*(NEIGHBOR+1)
#define KOUT    101           // NEGATIVE + TOTAL
#define DFEAT   512
#define NT      1024

// dynamic smem layout (byte offsets)
#define OFF_FKEY    0          // u64[2080]  16640
#define OFF_MKEY    16640      // u64[2048]  16384
#define OFF_EXTRA   33024      // u64[32]      256
#define OFF_MOM     33280      // u32[2080]   8320
#define OFF_RR      41600      // u8[2080]
#define OFF_CC      43680      // u8[2080]
#define OFF_SUP     45760      // u8[2080]
#define OFF_SEL     47840      // u8[2080]
#define OFF_UNSUP   49920      // u16[2080]   4160
#define OFF_SELIDX  54080      // u16[96]      192
#define OFF_WSUM    54272      // int[68]      272
#define OFF_FR      54544      // int[101]     404
#define OFF_FC      54948      // int[101]     404
#define OFF_WORDS   55352      // u32[65]      260
#define OFF_PFX     55612      // int[66]      264
#define OFF_PIV     55876      // int[4]        16
#define SMEM_BYTES  55936

typedef unsigned long long u64;

__device__ __forceinline__ void cas64(u64& a, u64& b, bool dir) {
    u64 x = a, y = b;
    bool sw = dir ? (x < y) : (x > y);
    a = sw ? y : x;
    b = sw ? x : y;
}

template<int J0>
__device__ __forceinline__ void reg_stages(u64 e[4], int tid, int lane, int k) {
    const int base = tid * 4;
    const bool dirU = ((base & k) == 0);
#pragma unroll
    for (int j = J0; j >= 4; j >>= 1) {
        int lm = j >> 2;
        bool lower = ((lane & lm) == 0);
        bool keepMax = (lower == dirU);
#pragma unroll
        for (int v = 0; v < 4; v++) {
            u64 p = __shfl_xor_sync(0xffffffffu, e[v], lm);
            u64 mx = e[v] > p ? e[v] : p;
            u64 mn = e[v] > p ? p : e[v];
            e[v] = keepMax ? mx : mn;
        }
    }
    if (J0 >= 2) {
        cas64(e[0], e[2], dirU);
        cas64(e[1], e[3], dirU);
    }
    if (k == 2) {
        cas64(e[0], e[1], true);
        cas64(e[2], e[3], false);
    } else {
        cas64(e[0], e[1], dirU);
        cas64(e[2], e[3], dirU);
    }
}

// Two levels (2j, j) of merge k over 2048 elems; 512 sorter threads.
__device__ __forceinline__ void pass2(u64* a, int k, int j, int lg, int tid) {
    int low  = tid & (j - 1);
    int hi   = tid >> lg;
    int base = (hi << (lg + 2)) | low;
    u64 e0 = a[base], e1 = a[base + j], e2 = a[base + 2 * j], e3 = a[base + 3 * j];
    bool dir = ((base & k) == 0);
    cas64(e0, e2, dir); cas64(e1, e3, dir);
    cas64(e0, e1, dir); cas64(e2, e3, dir);
    a[base] = e0; a[base + j] = e1; a[base + 2 * j] = e2; a[base + 3 * j] = e3;
}

__device__ __forceinline__ void single128(u64* a, int k, int tid) {
#pragma unroll
    for (int rep = 0; rep < 2; rep++) {
        int p = tid + rep * 512;
        int i = ((p >> 7) << 8) | (p & 127);
        u64 x = a[i], y = a[i + 128];
        bool dir = ((i & k) == 0);
        bool sw = dir ? (x < y) : (x > y);
        if (sw) { a[i] = y; a[i + 128] = x; }
    }
}

__global__ __launch_bounds__(NT, 1)
void aps_kernel(const float* __restrict__ score_pred,
                const float* __restrict__ map2d,
                const float* __restrict__ offset_gt,
                const float* __restrict__ tmap,
                float* __restrict__ out) {
    extern __shared__ char smem[];
    u64*  fkey  = (u64*)(smem + OFF_FKEY);
    u64*  mkey  = (u64*)(smem + OFF_MKEY);
    u64*  extra = (u64*)(smem + OFF_EXTRA);
    unsigned*       mom  = (unsigned*)      (smem + OFF_MOM);
    unsigned char*  rr   = (unsigned char*) (smem + OFF_RR);
    unsigned char*  cc   = (unsigned char*) (smem + OFF_CC);
    unsigned char*  sup  = (unsigned char*) (smem + OFF_SUP);
    unsigned char*  sel  = (unsigned char*) (smem + OFF_SEL);
    unsigned short* unsupIdx = (unsigned short*)(smem + OFF_UNSUP);
    unsigned short* selIdx   = (unsigned short*)(smem + OFF_SELIDX);
    int* wsum = (int*)(smem + OFF_WSUM);       // [0..32] unsup, [34..66] sel
    int* fr   = (int*)(smem + OFF_FR);
    int* fc   = (int*)(smem + OFF_FC);
    unsigned* words = (unsigned*)(smem + OFF_WORDS);
    int* pfx  = (int*)(smem + OFF_PFX);
    int* pivinfo = (int*)(smem + OFF_PIV);

    const int b    = blockIdx.x;
    const int tid  = threadIdx.x;
    const int lane = tid & 31, wid = tid >> 5;
    const bool sorter = (wid < 16);
    const unsigned lm_le = 0xffffffffu >> (31 - lane);   // lanes <= me

    // --- 1. (r,c) tables ---
    if (tid < NN) {
        int r = tid;
        int base = r * NN - (r * (r - 1)) / 2;
        for (int c = r; c < NN; c++) {
            int p = base + (c - r);
            rr[p] = (unsigned char)r;
            cc[p] = (unsigned char)c;
        }
    }
    __syncthreads();

    // --- 2. build keys in registers + clear bitmaps ---
    u64 e[4];
    if (sorter) {
#pragma unroll
        for (int v = 0; v < 4; v++) {
            int p = tid * 4 + v;
            int r = rr[p], c = cc[p];
            float s = score_pred[((size_t)b * NN + r) * NN + c];
            unsigned ub = __float_as_uint(s);
            ub = (ub & 0x80000000u) ? ~ub : (ub | 0x80000000u);
            e[v] = ((u64)ub << 32) | (unsigned)(2079 - p);
        }
    } else if (wid == 16) {
        int p = MAIN + lane;
        int r = rr[p], c = cc[p];
        float s = score_pred[((size_t)b * NN + r) * NN + c];
        unsigned ub = __float_as_uint(s);
        ub = (ub & 0x80000000u) ? ~ub : (ub | 0x80000000u);
        u64 x = ((u64)ub << 32) | (unsigned)(2079 - p);
#pragma unroll
        for (int k2 = 2; k2 <= 32; k2 <<= 1) {
            bool dirk = ((lane & k2) == 0);
#pragma unroll
            for (int j2 = 16; j2 >= 1; j2 >>= 1) {
                if (j2 < k2) {
                    u64 pr = __shfl_xor_sync(0xffffffffu, x, j2);
                    bool keepMax = (((lane & j2) == 0) == dirk);
                    u64 mx = x > pr ? x : pr;
                    u64 mn = x > pr ? pr : x;
                    x = keepMax ? mx : mn;
                }
            }
        }
        extra[lane] = x;
    }
    // clear sup/sel (touched only by NMS, much later)
    sup[tid] = 0; sel[tid] = 0;
    sup[tid + 1024] = 0; sel[tid + 1024] = 0;
    if (tid < 32) { sup[2048 + tid] = 0; sel[2048 + tid] = 0; }

    if (sorter) {
        reg_stages<1 >(e, tid, lane, 2);
        reg_stages<2 >(e, tid, lane, 4);
        reg_stages<4 >(e, tid, lane, 8);
        reg_stages<8 >(e, tid, lane, 16);
        reg_stages<16>(e, tid, lane, 32);
        reg_stages<32>(e, tid, lane, 64);
        reg_stages<64>(e, tid, lane, 128);
    }

    // --- 3. merges k=256..2048 ---
#pragma unroll 1
    for (int k = 256; k <= MAIN; k <<= 1) {
        if (sorter) {
#pragma unroll
            for (int v = 0; v < 4; v++) mkey[tid * 4 + v] = e[v];
        }
        __syncthreads();
        if (k == 256) {
            if (sorter) single128(mkey, k, tid);
        } else if (k == 512) {
            if (sorter) pass2(mkey, k, 128, 7, tid);
        } else if (k == 1024) {
            if (sorter) pass2(mkey, k, 256, 8, tid);
            __syncthreads();
            if (sorter) single128(mkey, k, tid);
        } else {
            if (sorter) pass2(mkey, k, 512, 9, tid);
            __syncthreads();
            if (sorter) pass2(mkey, k, 128, 7, tid);
        }
        __syncthreads();
        if (sorter) {
#pragma unroll
            for (int v = 0; v < 4; v++) e[v] = mkey[tid * 4 + v];
            reg_stages<64>(e, tid, lane, k);
        }
    }

    // --- 3d. publish + rank merge with extras; fused mom build ---
    if (sorter) {
#pragma unroll
        for (int v = 0; v < 4; v++) mkey[tid * 4 + v] = e[v];
    }
    __syncthreads();
    if (sorter) {
#pragma unroll
        for (int v = 0; v < 4; v++) {
            u64 x = e[v];
            int lo = 0, hiS = NEXTRA;
            while (lo < hiS) {
                int mid = (lo + hiS) >> 1;
                if (extra[mid] > x) lo = mid + 1; else hiS = mid;
            }
            int dst = tid * 4 + v + lo;
            fkey[dst] = x;
            int orig = 2079 - (int)(unsigned)(x & 0xFFFFFFFFull);
            mom[dst] = (unsigned)rr[orig] | (((unsigned)cc[orig] + 1u) << 16);
        }
    } else if (wid == 16) {
        u64 x = extra[lane];
        int lo = 0, hiS = MAIN;
        while (lo < hiS) {
            int mid = (lo + hiS) >> 1;
            if (mkey[mid] > x) lo = mid + 1; else hiS = mid;
        }
        int dst = lo + lane;
        fkey[dst] = x;
        int orig = 2079 - (int)(unsigned)(x & 0xFFFFFFFFull);
        mom[dst] = (unsigned)rr[orig] | (((unsigned)cc[orig] + 1u) << 16);
    }
    __syncthreads();

    // --- 4. cache moments in registers; publish first pivot (always 0) ---
    unsigned momA = mom[tid];
    unsigned momB = mom[tid + 1024];
    unsigned momC = (wid == 0) ? mom[2048 + tid] : 0u;
    if (tid == 0) { pivinfo[0] = 0; pivinfo[2] = (int)mom[0]; }
    __syncthreads();

    // --- 5. NMS: 2 barriers per pivot, register suppressed-bitmap in warp 0 ---
    unsigned cumA = 0, cumB = 0, cumC = 0;   // warp 0 only: words lane, 32+lane, 64
    bool m1p = false, m2p = false, m3p = false;
    int  r1p = 0, r2p = 0, r3p = 0;
#pragma unroll 1
    for (int iter = 0; iter <= TOPK; iter++) {
        int piv = pivinfo[0];
        // deferred writes for previous pivot
        if (m1p) { int rank = pfx[wid] + r1p;      sup[tid] = 1;        if (rank <= NEIGHBOR) sel[tid] = 1; }
        if (m2p) { int rank = pfx[32 + wid] + r2p; sup[tid + 1024] = 1; if (rank <= NEIGHBOR) sel[tid + 1024] = 1; }
        if (m3p) { int rank = pfx[64] + r3p;       sup[2048 + tid] = 1; if (rank <= NEIGHBOR) sel[2048 + tid] = 1; }
        if (iter == TOPK || piv < 0) break;

        unsigned mp = (unsigned)pivinfo[2];
        int s_i = (int)(mp & 0xffffu), e_i = (int)(mp >> 16);

        // phase A: matches from cached moments
        {
            int sj = (int)(momA & 0xffffu), ej = (int)(momA >> 16);
            int inter = min(ej, e_i) - max(sj, s_i);
            int uni   = max(ej, e_i) - min(sj, s_i);
            m1p = (2 * inter > uni) && (tid > piv);
        }
        {
            int sj = (int)(momB & 0xffffu), ej = (int)(momB >> 16);
            int inter = min(ej, e_i) - max(sj, s_i);
            int uni   = max(ej, e_i) - min(sj, s_i);
            m2p = (2 * inter > uni) && (tid + 1024 > piv);
        }
        unsigned b1 = __ballot_sync(0xffffffffu, m1p);
        unsigned b2 = __ballot_sync(0xffffffffu, m2p);
        r1p = __popc(b1 & lm_le);
        r2p = __popc(b2 & lm_le);
        if (lane == 0) { words[wid] = b1; words[32 + wid] = b2; }
        if (wid == 0) {
            int sj = (int)(momC & 0xffffu), ej = (int)(momC >> 16);
            int inter = min(ej, e_i) - max(sj, s_i);
            int uni   = max(ej, e_i) - min(sj, s_i);
            m3p = (2 * inter > uni) && (2048 + tid > piv);
            unsigned b3 = __ballot_sync(0xffffffffu, m3p);
            r3p = __popc(b3 & lm_le);
            if (lane == 0) words[64] = b3;
        } else { m3p = false; }
        __syncthreads();

        // phase B: warp 0 — prefix, cum bitmap, pivot sup/sel, next pivot
        if (wid == 0) {
            unsigned w0 = words[lane], w1 = words[32 + lane], wX = words[64];
            int c0 = __popc(w0), x0 = c0;
#pragma unroll
            for (int d = 1; d < 32; d <<= 1) {
                int y = __shfl_up_sync(0xffffffffu, x0, d);
                if (lane >= d) x0 += y;
            }
            pfx[lane] = x0 - c0;
            int tot0 = __shfl_sync(0xffffffffu, x0, 31);
            int c1 = __popc(w1), x1 = c1;
#pragma unroll
            for (int d = 1; d < 32; d <<= 1) {
                int y = __shfl_up_sync(0xffffffffu, x1, d);
                if (lane >= d) x1 += y;
            }
            pfx[32 + lane] = tot0 + x1 - c1;
            if (lane == 31) pfx[64] = tot0 + x1;

            cumA |= w0; cumB |= w1;
            if (lane == 0) cumC |= wX;
            int pw = piv >> 5, pb = piv & 31;
            if (pw < 32)      { if (lane == pw)      cumA |= (1u << pb); }
            else if (pw < 64) { if (lane == pw - 32) cumB |= (1u << pb); }
            else              { if (lane == 0)       cumC |= (1u << pb); }
            if (lane == 0) { sup[piv] = 1; sel[piv] = 1; }

            // next pivot = first free index < MV-1
            unsigned fA = ~cumA;
            unsigned balA = __ballot_sync(0xffffffffu, fA != 0u);
            int npiv = -1;
            if (balA) {
                int l0 = __ffs(balA) - 1;
                unsigned f = __shfl_sync(0xffffffffu, fA, l0);
                npiv = l0 * 32 + __ffs(f) - 1;
            } else {
                unsigned fB = ~cumB;
                unsigned balB = __ballot_sync(0xffffffffu, fB != 0u);
                if (balB) {
                    int l0 = __ffs(balB) - 1;
                    unsigned f = __shfl_sync(0xffffffffu, fB, l0);
                    npiv = (32 + l0) * 32 + __ffs(f) - 1;
                } else {
                    unsigned fC = (~cumC) & 0x7fffffffu;   // exclude j = 2079
                    fC = __shfl_sync(0xffffffffu, fC, 0);
                    if (fC) npiv = 2048 + __ffs(fC) - 1;
                }
            }
            if (lane == 0) {
                pivinfo[0] = npiv;
                if (npiv >= 0) pivinfo[2] = (int)mom[npiv];
            }
        }
        __syncthreads();
    }
    __syncthreads();

    // --- 6. fused dual compaction ( !sup -> unsupIdx , sel -> selIdx ) ---
    bool pU[3], pS[3]; int lU = 0, lS = 0;
#pragma unroll
    for (int u = 0; u < 3; u++) {
        int j = 3 * tid + u;
        bool valid = (j < MV);
        unsigned char sv = valid ? sup[j] : 1;
        unsigned char ev = valid ? sel[j] : 0;
        pU[u] = valid && (sv == 0);
        pS[u] = valid && (ev != 0);
        lU += (int)pU[u]; lS += (int)pS[u];
    }
    int xU = lU, xS = lS;
#pragma unroll
    for (int d = 1; d < 32; d <<= 1) {
        int yU = __shfl_up_sync(0xffffffffu, xU, d);
        int yS = __shfl_up_sync(0xffffffffu, xS, d);
        if (lane >= d) { xU += yU; xS += yS; }
    }
    if (lane == 31) { wsum[wid] = xU; wsum[34 + wid] = xS; }
    __syncthreads();
    if (wid == 0) {
        int vU = wsum[lane], vS = wsum[34 + lane];
        int xxU = vU, xxS = vS;
#pragma unroll
        for (int d = 1; d < 32; d <<= 1) {
            int yU = __shfl_up_sync(0xffffffffu, xxU, d);
            int yS = __shfl_up_sync(0xffffffffu, xxS, d);
            if (lane >= d) { xxU += yU; xxS += yS; }
        }
        wsum[lane] = xxU - vU;
        wsum[34 + lane] = xxS - vS;
        if (lane == 31) { wsum[32] = xxU; wsum[66] = xxS; }
    }
    __syncthreads();
    {
        int baseU = wsum[wid] + xU - lU;
        int baseS = wsum[34 + wid] + xS - lS;
#pragma unroll
        for (int u = 0; u < 3; u++) {
            if (pU[u]) unsupIdx[baseU++] = (unsigned short)(3 * tid + u);
            if (pS[u]) selIdx[baseS++]   = (unsigned short)(3 * tid + u);
        }
    }
    int nUnsup = wsum[32];
    int nSel   = wsum[66];
    __syncthreads();

    // --- 7. final index assembly + small outputs ---
    float* feat = out;
    float* se   = out + (size_t)NB * KOUT * DFEAT;
    float* off  = se  + (size_t)NB * KOUT * 2;
    float* sc   = off + (size_t)NB * KOUT * 2;

    if (tid < KOUT) {
        int k = tid;
        int val;
        if (k < NEGATIVE) {
            int pos = nUnsup - 1 - k;
            if (pos < 0) pos = 0;
            val = (pos < nUnsup) ? (int)unsupIdx[pos] : (MV - 1);
        } else {
            int p = k - NEGATIVE;
            int pad = TOTAL - nSel;
            if (p < pad) {
                val = (p < nUnsup) ? (int)unsupIdx[p] : (MV - 1);
            } else {
                val = (int)selIdx[p - pad];
            }
        }
        int orig = 2079 - (int)(unsigned)(fkey[val] & 0xFFFFFFFFull);
        int r = rr[orig], c = cc[orig];
        fr[k] = r; fc[k] = c;

        size_t o = (size_t)b * KOUT + k;
        se[o * 2 + 0] = (float)r;
        se[o * 2 + 1] = (float)(c + 1);
        size_t cell = ((size_t)b * NN + r) * NN + c;
        off[o * 2 + 0] = offset_gt[cell * 2 + 0];
        off[o * 2 + 1] = offset_gt[cell * 2 + 1];
        sc[o] = tmap[cell];
    }
    __syncthreads();

    // --- 8. feature gather (float4) ---
    const float4* src = (const float4*)map2d;
    float4* dst = (float4*)feat;
    const int VEC = DFEAT / 4;   // 128
    for (int t = tid; t < KOUT * VEC; t += NT) {
        int k = t >> 7;
        int d = t & (VEC - 1);
        int r = fr[k], c = fc[k];
        dst[((size_t)b * KOUT + k) * VEC + d] =
            src[(((size_t)b * NN + r) * NN + c) * VEC + d];
    }
}

extern "C" void kernel_launch(void* const* d_in, const int* in_sizes, int n_in,
                              void* d_out, int out_size) {
    const float* score_pred = (const float*)d_in[0];
    // d_in[1] = map2d_mask (deterministic triu(ones)) — computed analytically
    const float* map2d      = (const float*)d_in[2];
    const float* offset_gt  = (const float*)d_in[3];
    const float* tmap       = (const float*)d_in[4];
    float* out = (float*)d_out;

    cudaFuncSetAttribute(aps_kernel, cudaFuncAttributeMaxDynamicSharedMemorySize,
                         SMEM_BYTES);
    aps_kernel<<<NB, NT, SMEM_BYTES>>>(score_pred, map2d, offset_gt, tmap, out);
}